// round 7
// baseline (speedup 1.0000x reference)
#include <cuda_runtime.h>
#include <cuda_bf16.h>
#include <cstdint>

// ============================================================================
// InfoNCE loss, both directions. normalize->bf16, 128x256 CTA-tile HMMA GEMM
// (warp tile 64x64, double-buffered cp.async over K), fused exp + row/col
// sums, final log-reduce.
// ============================================================================
#define BATCH 16
#define NROWS 2048
#define DIMC  256
#define TOTAL_ROWS (BATCH * NROWS)            // 32768
#define TEMP_INV   10.0f

#define TILE_M 128
#define TILE_N 256
#define KC     64                              // K chunk
#define NSTEPS (DIMC / KC)                     // 4

// warp grid: 2 (M) x 4 (N); warp tile 64x64
#define WM 64
#define WN 64

// Smem rows: KC bf16 + 8 pad = 144 B (conflict-free ldmatrix, proven R5/R6)
#define LDS_ROW_B 144
#define A_STAGE_BYTES (TILE_M * LDS_ROW_B)     // 18432
#define B_STAGE_BYTES (TILE_N * LDS_ROW_B)     // 36864
#define STAGE_BYTES   (A_STAGE_BYTES + B_STAGE_BYTES)  // 55296
#define SMEM_TOTAL    (2 * STAGE_BYTES)        // 110592

// ============================================================================
// Device scratch
// ============================================================================
__device__ __align__(16) __nv_bfloat16 g_Abf[TOTAL_ROWS * DIMC];
__device__ __align__(16) __nv_bfloat16 g_Bbf[TOTAL_ROWS * DIMC];
__device__ float g_rowSum[TOTAL_ROWS];
__device__ float g_colSum[TOTAL_ROWS];
__device__ float g_diag[TOTAL_ROWS];

// ============================================================================
// Helpers
// ============================================================================
__device__ __forceinline__ uint32_t smem_u32(const void* p) {
    uint32_t a;
    asm("{ .reg .u64 t; cvta.to.shared.u64 t, %1; cvt.u32.u64 %0, t; }"
        : "=r"(a) : "l"(p));
    return a;
}

__device__ __forceinline__ uint32_t pack_bf16x2(float lo, float hi) {
    uint32_t r;
    asm("cvt.rn.bf16x2.f32 %0, %1, %2;" : "=r"(r) : "f"(hi), "f"(lo));
    return r;
}

#define CP_ASYNC16(dst, src) \
    asm volatile("cp.async.cg.shared.global [%0], [%1], 16;" :: "r"(dst), "l"(src))
#define CP_COMMIT() asm volatile("cp.async.commit_group;")
#define CP_WAIT(n)  asm volatile("cp.async.wait_group %0;" :: "n"(n) : "memory")

__device__ __forceinline__ void ldmatrix_x4(uint32_t& r0, uint32_t& r1,
                                            uint32_t& r2, uint32_t& r3,
                                            uint32_t addr) {
    asm volatile("ldmatrix.sync.aligned.m8n8.x4.shared.b16 {%0,%1,%2,%3}, [%4];"
                 : "=r"(r0), "=r"(r1), "=r"(r2), "=r"(r3) : "r"(addr));
}

__device__ __forceinline__ void mma_bf16(float* d, const uint32_t* a,
                                         const uint32_t* b, const float* c) {
    asm volatile(
        "mma.sync.aligned.m16n8k16.row.col.f32.bf16.bf16.f32 "
        "{%0,%1,%2,%3}, {%4,%5,%6,%7}, {%8,%9}, {%10,%11,%12,%13};"
        : "=f"(d[0]), "=f"(d[1]), "=f"(d[2]), "=f"(d[3])
        : "r"(a[0]), "r"(a[1]), "r"(a[2]), "r"(a[3]),
          "r"(b[0]), "r"(b[1]),
          "f"(c[0]), "f"(c[1]), "f"(c[2]), "f"(c[3]));
}

// ============================================================================
// Kernel 1: L2-normalize rows -> bf16; zero accumulators + out
// ============================================================================
__global__ void normalize_kernel(const float* __restrict__ A,
                                 const float* __restrict__ B,
                                 float* out) {
    int gwarp = (blockIdx.x * blockDim.x + threadIdx.x) >> 5;
    int lane = threadIdx.x & 31;
    if (gwarp >= 2 * TOTAL_ROWS) return;

    const float* src;
    __nv_bfloat16* dst;
    int row;
    if (gwarp < TOTAL_ROWS) {
        src = A; dst = g_Abf; row = gwarp;
        if (lane == 0) { g_rowSum[row] = 0.0f; g_colSum[row] = 0.0f; }
        if (gwarp == 0 && lane == 1) out[0] = 0.0f;
    } else {
        src = B; dst = g_Bbf; row = gwarp - TOTAL_ROWS;
    }

    const float4* p = reinterpret_cast<const float4*>(src + (size_t)row * DIMC);
    float4 v0 = p[lane * 2];
    float4 v1 = p[lane * 2 + 1];
    float ss = v0.x*v0.x + v0.y*v0.y + v0.z*v0.z + v0.w*v0.w
             + v1.x*v1.x + v1.y*v1.y + v1.z*v1.z + v1.w*v1.w;
    #pragma unroll
    for (int off = 16; off > 0; off >>= 1)
        ss += __shfl_xor_sync(0xFFFFFFFFu, ss, off);
    float rinv = rsqrtf(ss);

    uint32_t o0 = pack_bf16x2(v0.x * rinv, v0.y * rinv);
    uint32_t o1 = pack_bf16x2(v0.z * rinv, v0.w * rinv);
    uint32_t o2 = pack_bf16x2(v1.x * rinv, v1.y * rinv);
    uint32_t o3 = pack_bf16x2(v1.z * rinv, v1.w * rinv);
    reinterpret_cast<uint4*>(dst + (size_t)row * DIMC)[lane] =
        make_uint4(o0, o1, o2, o3);
}

// ============================================================================
// Kernel 2: 128x256 tile GEMM (HMMA bf16), double-buffered over K,
// fused exp + row/col reductions.  grid=(8,16,16) block=256 (8 warps)
// ============================================================================
__device__ __forceinline__ void stage_issue(uint32_t sbase, int stage, int kc0,
                                            const __nv_bfloat16* gA,
                                            const __nv_bfloat16* gB, int tid) {
    uint32_t aDst = sbase + (uint32_t)stage * STAGE_BYTES;
    uint32_t bDst = aDst + A_STAGE_BYTES;
    // A: 128 rows x 8 chunks = 1024 -> 4/thread
    #pragma unroll
    for (int t = 0; t < 4; t++) {
        int i = tid + t * 256;
        int row = i >> 3;
        int c16 = i & 7;
        CP_ASYNC16(aDst + (uint32_t)row * LDS_ROW_B + c16 * 16,
                   gA + (size_t)row * DIMC + kc0 + c16 * 8);
    }
    // B: 256 rows x 8 chunks = 2048 -> 8/thread
    #pragma unroll
    for (int t = 0; t < 8; t++) {
        int i = tid + t * 256;
        int row = i >> 3;
        int c16 = i & 7;
        CP_ASYNC16(bDst + (uint32_t)row * LDS_ROW_B + c16 * 16,
                   gB + (size_t)row * DIMC + kc0 + c16 * 8);
    }
    CP_COMMIT();
}

__global__ void __launch_bounds__(256, 1)
gemm_nce_kernel() {
    extern __shared__ char smem[];
    uint32_t sbase = smem_u32(smem);
    int tid  = threadIdx.x;
    int wid  = tid >> 5;
    int lane = tid & 31;

    int b  = blockIdx.z;
    int m0 = blockIdx.y * TILE_M;
    int n0 = blockIdx.x * TILE_N;

    const __nv_bfloat16* gA = g_Abf + ((size_t)b * NROWS + m0) * DIMC;
    const __nv_bfloat16* gB = g_Bbf + ((size_t)b * NROWS + n0) * DIMC;

    int warp_m = wid & 1;               // 0..1 (64 rows)
    int warp_n = wid >> 1;              // 0..3 (64 cols)

    float acc[4][8][4];                 // [tm][tn][reg]  (m16 x n8 tiles)
    #pragma unroll
    for (int tm = 0; tm < 4; tm++)
        #pragma unroll
        for (int tn = 0; tn < 8; tn++)
            #pragma unroll
            for (int r = 0; r < 4; r++) acc[tm][tn][r] = 0.0f;

    int lm_row_a = lane & 15;
    int lm_koff_a = (lane >> 4) << 3;
    int lm_row_b = ((lane >> 4) << 3) + (lane & 7);
    int lm_koff_b = ((lane >> 3) & 1) << 3;

    stage_issue(sbase, 0, 0, gA, gB, tid);

    #pragma unroll
    for (int s = 0; s < NSTEPS; s++) {
        if (s + 1 < NSTEPS) {
            stage_issue(sbase, (s + 1) & 1, (s + 1) * KC, gA, gB, tid);
            CP_WAIT(1);
        } else {
            CP_WAIT(0);
        }
        __syncthreads();

        uint32_t aBase = sbase + (uint32_t)(s & 1) * STAGE_BYTES
                       + (uint32_t)(warp_m * WM) * LDS_ROW_B;
        uint32_t bBase = sbase + (uint32_t)(s & 1) * STAGE_BYTES + A_STAGE_BYTES
                       + (uint32_t)(warp_n * WN) * LDS_ROW_B;

        #pragma unroll
        for (int ks = 0; ks < KC / 16; ks++) {
            int k0 = ks * 16;
            // B frags: 4 halves of n16 -> 8 n8 tiles
            uint32_t bf[8][2];
            #pragma unroll
            for (int half = 0; half < 4; half++) {
                uint32_t addr = bBase
                    + (uint32_t)(half * 16 + lm_row_b) * LDS_ROW_B
                    + (uint32_t)(k0 + lm_koff_b) * 2;
                ldmatrix_x4(bf[half*2][0], bf[half*2][1],
                            bf[half*2+1][0], bf[half*2+1][1], addr);
            }
            // A frags per m16 tile; 8 MMAs each
            #pragma unroll
            for (int tm = 0; tm < 4; tm++) {
                uint32_t af[4];
                uint32_t addr = aBase
                    + (uint32_t)(tm * 16 + lm_row_a) * LDS_ROW_B
                    + (uint32_t)(k0 + lm_koff_a) * 2;
                ldmatrix_x4(af[0], af[1], af[2], af[3], addr);
                #pragma unroll
                for (int tn = 0; tn < 8; tn++)
                    mma_bf16(acc[tm][tn], af, bf[tn], acc[tm][tn]);
            }
        }
        __syncthreads();
    }

    // ---- Epilogue ----
    int rbase = warp_m * WM;
    int cbase = warp_n * WN;
    int rlane = lane >> 2;
    int clane = (lane & 3) * 2;

    float rowAcc[4][2];
    float colAcc[8][2];
    #pragma unroll
    for (int i = 0; i < 4; i++) { rowAcc[i][0] = rowAcc[i][1] = 0.f; }
    #pragma unroll
    for (int i = 0; i < 8; i++) { colAcc[i][0] = colAcc[i][1] = 0.f; }

    #pragma unroll
    for (int tm = 0; tm < 4; tm++) {
        #pragma unroll
        for (int tn = 0; tn < 8; tn++) {
            #pragma unroll
            for (int r = 0; r < 4; r++) {
                int h = r >> 1, j = r & 1;
                float sim = TEMP_INV * acc[tm][tn][r];
                int gr = m0 + rbase + tm*16 + rlane + 8*h;   // global row
                int gc = n0 + cbase + tn*8 + clane + j;      // global col
                if (gr == gc)
                    g_diag[(b << 11) + gr] = sim;
                float e = __expf(sim);
                rowAcc[tm][h] += e;
                colAcc[tn][j] += e;
            }
        }
    }

    // row sums: reduce over lane%4
    #pragma unroll
    for (int tm = 0; tm < 4; tm++)
        #pragma unroll
        for (int h = 0; h < 2; h++) {
            float v = rowAcc[tm][h];
            v += __shfl_xor_sync(0xFFFFFFFFu, v, 1);
            v += __shfl_xor_sync(0xFFFFFFFFu, v, 2);
            if ((lane & 3) == 0) {
                int lr = rbase + tm*16 + rlane + 8*h;
                atomicAdd(&g_rowSum[(b << 11) + m0 + lr], v);
            }
        }

    // col sums: reduce over lane/4
    #pragma unroll
    for (int tn = 0; tn < 8; tn++)
        #pragma unroll
        for (int j = 0; j < 2; j++) {
            float v = colAcc[tn][j];
            v += __shfl_xor_sync(0xFFFFFFFFu, v, 4);
            v += __shfl_xor_sync(0xFFFFFFFFu, v, 8);
            v += __shfl_xor_sync(0xFFFFFFFFu, v, 16);
            if (lane < 4) {
                int lc = cbase + tn*8 + clane + j;
                atomicAdd(&g_colSum[(b << 11) + n0 + lc], v);
            }
        }
}

// ============================================================================
// Kernel 3: final reduction  loss = mean(log rowSum + log colSum - 2*diag)
// ============================================================================
__global__ void reduce_kernel(float* out) {
    __shared__ float red[8];
    int i = blockIdx.x * blockDim.x + threadIdx.x;
    float v = 0.0f;
    if (i < TOTAL_ROWS)
        v = logf(g_rowSum[i]) + logf(g_colSum[i]) - 2.0f * g_diag[i];
    #pragma unroll
    for (int off = 16; off > 0; off >>= 1)
        v += __shfl_xor_sync(0xFFFFFFFFu, v, off);
    int lane = threadIdx.x & 31, wid = threadIdx.x >> 5;
    if (lane == 0) red[wid] = v;
    __syncthreads();
    if (wid == 0) {
        v = (lane < 8) ? red[lane] : 0.0f;
        #pragma unroll
        for (int off = 4; off > 0; off >>= 1)
            v += __shfl_xor_sync(0xFFFFFFFFu, v, off);
        if (lane == 0) atomicAdd(out, v * (1.0f / TOTAL_ROWS));
    }
}

// ============================================================================
// Launch
// ============================================================================
extern "C" void kernel_launch(void* const* d_in, const int* in_sizes, int n_in,
                              void* d_out, int out_size) {
    const float* A = (const float*)d_in[0];
    const float* B = (const float*)d_in[1];
    float* out = (float*)d_out;

    cudaFuncSetAttribute(gemm_nce_kernel,
                         cudaFuncAttributeMaxDynamicSharedMemorySize, SMEM_TOTAL);

    normalize_kernel<<<(2 * TOTAL_ROWS) / 8, 256>>>(A, B, out);

    dim3 grid(NROWS / TILE_N, NROWS / TILE_M, BATCH);   // (8, 16, 16)
    gemm_nce_kernel<<<grid, 256, SMEM_TOTAL>>>();

    reduce_kernel<<<(TOTAL_ROWS + 255) / 256, 256>>>(out);
}

// round 10
// speedup vs baseline: 1.0922x; 1.0922x over previous
#include <cuda_runtime.h>
#include <cuda_bf16.h>
#include <cstdint>

// ============================================================================
// InfoNCE loss, both directions. normalize->bf16; 128x128 CTA-tile HMMA GEMM,
// 4 warps x (64x64) warp tiles, double-buffered cp.async over K, 2 CTAs/SM;
// fused exp + row/col sums; final log-reduce.
// ============================================================================
#define BATCH 16
#define NROWS 2048
#define DIMC  256
#define TOTAL_ROWS (BATCH * NROWS)            // 32768
#define TEMP_INV   10.0f

#define TILE_M 128
#define TILE_N 128
#define KC     64                              // K chunk
#define NSTEPS (DIMC / KC)                     // 4

// warp grid: 2 (M) x 2 (N); warp tile 64x64
#define WM 64
#define WN 64

// Smem rows: KC bf16 + 8 pad = 144 B (conflict-free ldmatrix, proven R5/R6)
#define LDS_ROW_B 144
#define A_STAGE_BYTES (TILE_M * LDS_ROW_B)     // 18432
#define STAGE_BYTES   (2 * A_STAGE_BYTES)      // 36864 (A then B)
#define SMEM_TOTAL    (2 * STAGE_BYTES)        // 73728

// ============================================================================
// Device scratch
// ============================================================================
__device__ __align__(16) __nv_bfloat16 g_Abf[TOTAL_ROWS * DIMC];
__device__ __align__(16) __nv_bfloat16 g_Bbf[TOTAL_ROWS * DIMC];
__device__ float g_rowSum[TOTAL_ROWS];
__device__ float g_colSum[TOTAL_ROWS];
__device__ float g_diag[TOTAL_ROWS];

// ============================================================================
// Helpers
// ============================================================================
__device__ __forceinline__ uint32_t smem_u32(const void* p) {
    uint32_t a;
    asm("{ .reg .u64 t; cvta.to.shared.u64 t, %1; cvt.u32.u64 %0, t; }"
        : "=r"(a) : "l"(p));
    return a;
}

__device__ __forceinline__ uint32_t pack_bf16x2(float lo, float hi) {
    uint32_t r;
    asm("cvt.rn.bf16x2.f32 %0, %1, %2;" : "=r"(r) : "f"(hi), "f"(lo));
    return r;
}

#define CP_ASYNC16(dst, src) \
    asm volatile("cp.async.cg.shared.global [%0], [%1], 16;" :: "r"(dst), "l"(src))
#define CP_COMMIT() asm volatile("cp.async.commit_group;")
#define CP_WAIT(n)  asm volatile("cp.async.wait_group %0;" :: "n"(n) : "memory")

__device__ __forceinline__ void ldmatrix_x4(uint32_t& r0, uint32_t& r1,
                                            uint32_t& r2, uint32_t& r3,
                                            uint32_t addr) {
    asm volatile("ldmatrix.sync.aligned.m8n8.x4.shared.b16 {%0,%1,%2,%3}, [%4];"
                 : "=r"(r0), "=r"(r1), "=r"(r2), "=r"(r3) : "r"(addr));
}

__device__ __forceinline__ void mma_bf16(float* d, const uint32_t* a,
                                         const uint32_t* b, const float* c) {
    asm volatile(
        "mma.sync.aligned.m16n8k16.row.col.f32.bf16.bf16.f32 "
        "{%0,%1,%2,%3}, {%4,%5,%6,%7}, {%8,%9}, {%10,%11,%12,%13};"
        : "=f"(d[0]), "=f"(d[1]), "=f"(d[2]), "=f"(d[3])
        : "r"(a[0]), "r"(a[1]), "r"(a[2]), "r"(a[3]),
          "r"(b[0]), "r"(b[1]),
          "f"(c[0]), "f"(c[1]), "f"(c[2]), "f"(c[3]));
}

// ============================================================================
// Kernel 1: L2-normalize rows -> bf16; zero accumulators + out
// ============================================================================
__global__ void normalize_kernel(const float* __restrict__ A,
                                 const float* __restrict__ B,
                                 float* out) {
    int gwarp = (blockIdx.x * blockDim.x + threadIdx.x) >> 5;
    int lane = threadIdx.x & 31;
    if (gwarp >= 2 * TOTAL_ROWS) return;

    const float* src;
    __nv_bfloat16* dst;
    int row;
    if (gwarp < TOTAL_ROWS) {
        src = A; dst = g_Abf; row = gwarp;
        if (lane == 0) { g_rowSum[row] = 0.0f; g_colSum[row] = 0.0f; }
        if (gwarp == 0 && lane == 1) out[0] = 0.0f;
    } else {
        src = B; dst = g_Bbf; row = gwarp - TOTAL_ROWS;
    }

    const float4* p = reinterpret_cast<const float4*>(src + (size_t)row * DIMC);
    float4 v0 = p[lane * 2];
    float4 v1 = p[lane * 2 + 1];
    float ss = v0.x*v0.x + v0.y*v0.y + v0.z*v0.z + v0.w*v0.w
             + v1.x*v1.x + v1.y*v1.y + v1.z*v1.z + v1.w*v1.w;
    #pragma unroll
    for (int off = 16; off > 0; off >>= 1)
        ss += __shfl_xor_sync(0xFFFFFFFFu, ss, off);
    float rinv = rsqrtf(ss);

    uint32_t o0 = pack_bf16x2(v0.x * rinv, v0.y * rinv);
    uint32_t o1 = pack_bf16x2(v0.z * rinv, v0.w * rinv);
    uint32_t o2 = pack_bf16x2(v1.x * rinv, v1.y * rinv);
    uint32_t o3 = pack_bf16x2(v1.z * rinv, v1.w * rinv);
    reinterpret_cast<uint4*>(dst + (size_t)row * DIMC)[lane] =
        make_uint4(o0, o1, o2, o3);
}

// ============================================================================
// Kernel 2: 128x128 tile GEMM (HMMA bf16), 4 warps x 64x64, double-buffered,
// fused exp + row/col reductions.  grid=(16,16,16), block=128, 2 CTA/SM
// ============================================================================
__device__ __forceinline__ void stage_issue(uint32_t sbase, int stage, int kc0,
                                            const __nv_bfloat16* gA,
                                            const __nv_bfloat16* gB, int tid) {
    uint32_t aDst = sbase + (uint32_t)stage * STAGE_BYTES;
    uint32_t bDst = aDst + A_STAGE_BYTES;
    // per operand: 128 rows x 8 chunks of 16B = 1024 chunks -> 8/thread
    #pragma unroll
    for (int t = 0; t < 8; t++) {
        int i = tid + t * 128;
        int row = i >> 3;
        int c16 = i & 7;
        uint32_t so = (uint32_t)row * LDS_ROW_B + c16 * 16;
        CP_ASYNC16(aDst + so, gA + (size_t)row * DIMC + kc0 + c16 * 8);
        CP_ASYNC16(bDst + so, gB + (size_t)row * DIMC + kc0 + c16 * 8);
    }
    CP_COMMIT();
}

__global__ void __launch_bounds__(128, 2)
gemm_nce_kernel() {
    extern __shared__ char smem[];
    uint32_t sbase = smem_u32(smem);
    int tid  = threadIdx.x;
    int wid  = tid >> 5;
    int lane = tid & 31;

    int b  = blockIdx.z;
    int m0 = blockIdx.y * TILE_M;
    int n0 = blockIdx.x * TILE_N;

    const __nv_bfloat16* gA = g_Abf + ((size_t)b * NROWS + m0) * DIMC;
    const __nv_bfloat16* gB = g_Bbf + ((size_t)b * NROWS + n0) * DIMC;

    int warp_m = wid & 1;               // 0..1 (64 rows)
    int warp_n = wid >> 1;              // 0..1 (64 cols)

    float acc[4][8][4];                 // [tm][tn][reg]  (m16 x n8 tiles)
    #pragma unroll
    for (int tm = 0; tm < 4; tm++)
        #pragma unroll
        for (int tn = 0; tn < 8; tn++)
            #pragma unroll
            for (int r = 0; r < 4; r++) acc[tm][tn][r] = 0.0f;

    int lm_row_a = lane & 15;
    int lm_koff_a = (lane >> 4) << 3;
    int lm_row_b = ((lane >> 4) << 3) + (lane & 7);
    int lm_koff_b = ((lane >> 3) & 1) << 3;

    stage_issue(sbase, 0, 0, gA, gB, tid);

    #pragma unroll
    for (int s = 0; s < NSTEPS; s++) {
        if (s + 1 < NSTEPS) {
            stage_issue(sbase, (s + 1) & 1, (s + 1) * KC, gA, gB, tid);
            CP_WAIT(1);
        } else {
            CP_WAIT(0);
        }
        __syncthreads();

        uint32_t aBase = sbase + (uint32_t)(s & 1) * STAGE_BYTES
                       + (uint32_t)(warp_m * WM) * LDS_ROW_B;
        uint32_t bBase = sbase + (uint32_t)(s & 1) * STAGE_BYTES + A_STAGE_BYTES
                       + (uint32_t)(warp_n * WN) * LDS_ROW_B;

        #pragma unroll
        for (int ks = 0; ks < KC / 16; ks++) {
            int k0 = ks * 16;
            // B frags: 4 n16 halves -> 8 n8 tiles
            uint32_t bf[8][2];
            #pragma unroll
            for (int half = 0; half < 4; half++) {
                uint32_t addr = bBase
                    + (uint32_t)(half * 16 + lm_row_b) * LDS_ROW_B
                    + (uint32_t)(k0 + lm_koff_b) * 2;
                ldmatrix_x4(bf[half*2][0], bf[half*2][1],
                            bf[half*2+1][0], bf[half*2+1][1], addr);
            }
            // A frags per m16 tile; 8 MMAs each
            #pragma unroll
            for (int tm = 0; tm < 4; tm++) {
                uint32_t af[4];
                uint32_t addr = aBase
                    + (uint32_t)(tm * 16 + lm_row_a) * LDS_ROW_B
                    + (uint32_t)(k0 + lm_koff_a) * 2;
                ldmatrix_x4(af[0], af[1], af[2], af[3], addr);
                #pragma unroll
                for (int tn = 0; tn < 8; tn++)
                    mma_bf16(acc[tm][tn], af, bf[tn], acc[tm][tn]);
            }
        }
        __syncthreads();
    }

    // ---- Epilogue: sim = 10*acc; exp; row/col sums; diag ----
    int rbase = warp_m * WM;
    int cbase = warp_n * WN;
    int rlane = lane >> 2;
    int clane = (lane & 3) * 2;

    float rowAcc[4][2];
    float colAcc[8][2];
    #pragma unroll
    for (int i = 0; i < 4; i++) { rowAcc[i][0] = rowAcc[i][1] = 0.f; }
    #pragma unroll
    for (int i = 0; i < 8; i++) { colAcc[i][0] = colAcc[i][1] = 0.f; }

    #pragma unroll
    for (int tm = 0; tm < 4; tm++) {
        #pragma unroll
        for (int tn = 0; tn < 8; tn++) {
            #pragma unroll
            for (int r = 0; r < 4; r++) {
                int h = r >> 1, j = r & 1;
                float sim = TEMP_INV * acc[tm][tn][r];
                int gr = m0 + rbase + tm*16 + rlane + 8*h;
                int gc = n0 + cbase + tn*8 + clane + j;
                if (gr == gc)
                    g_diag[(b << 11) + gr] = sim;
                float e = __expf(sim);
                rowAcc[tm][h] += e;
                colAcc[tn][j] += e;
            }
        }
    }

    // row sums: reduce over lane%4
    #pragma unroll
    for (int tm = 0; tm < 4; tm++)
        #pragma unroll
        for (int h = 0; h < 2; h++) {
            float v = rowAcc[tm][h];
            v += __shfl_xor_sync(0xFFFFFFFFu, v, 1);
            v += __shfl_xor_sync(0xFFFFFFFFu, v, 2);
            if ((lane & 3) == 0) {
                int lr = rbase + tm*16 + rlane + 8*h;
                atomicAdd(&g_rowSum[(b << 11) + m0 + lr], v);
            }
        }

    // col sums: reduce over lane/4
    #pragma unroll
    for (int tn = 0; tn < 8; tn++)
        #pragma unroll
        for (int j = 0; j < 2; j++) {
            float v = colAcc[tn][j];
            v += __shfl_xor_sync(0xFFFFFFFFu, v, 4);
            v += __shfl_xor_sync(0xFFFFFFFFu, v, 8);
            v += __shfl_xor_sync(0xFFFFFFFFu, v, 16);
            if (lane < 4) {
                int lc = cbase + tn*8 + clane + j;
                atomicAdd(&g_colSum[(b << 11) + n0 + lc], v);
            }
        }
}

// ============================================================================
// Kernel 3: final reduction  loss = mean(log rowSum + log colSum - 2*diag)
// ============================================================================
__global__ void reduce_kernel(float* out) {
    __shared__ float red[8];
    int i = blockIdx.x * blockDim.x + threadIdx.x;
    float v = 0.0f;
    if (i < TOTAL_ROWS)
        v = logf(g_rowSum[i]) + logf(g_colSum[i]) - 2.0f * g_diag[i];
    #pragma unroll
    for (int off = 16; off > 0; off >>= 1)
        v += __shfl_xor_sync(0xFFFFFFFFu, v, off);
    int lane = threadIdx.x & 31, wid = threadIdx.x >> 5;
    if (lane == 0) red[wid] = v;
    __syncthreads();
    if (wid == 0) {
        v = (lane < 8) ? red[lane] : 0.0f;
        #pragma unroll
        for (int off = 4; off > 0; off >>= 1)
            v += __shfl_xor_sync(0xFFFFFFFFu, v, off);
        if (lane == 0) atomicAdd(out, v * (1.0f / TOTAL_ROWS));
    }
}

// ============================================================================
// Launch
// ============================================================================
extern "C" void kernel_launch(void* const* d_in, const int* in_sizes, int n_in,
                              void* d_out, int out_size) {
    const float* A = (const float*)d_in[0];
    const float* B = (const float*)d_in[1];
    float* out = (float*)d_out;

    cudaFuncSetAttribute(gemm_nce_kernel,
                         cudaFuncAttributeMaxDynamicSharedMemorySize, SMEM_TOTAL);

    normalize_kernel<<<(2 * TOTAL_ROWS) / 8, 256>>>(A, B, out);

    dim3 grid(NROWS / TILE_N, NROWS / TILE_M, BATCH);   // (16, 16, 16)
    gemm_nce_kernel<<<grid, 128, SMEM_TOTAL>>>();

    reduce_kernel<<<(TOTAL_ROWS + 255) / 256, 256>>>(out);
}

// round 11
// speedup vs baseline: 1.2320x; 1.1280x over previous
#include <cuda_runtime.h>
#include <cuda_bf16.h>
#include <cstdint>

// ============================================================================
// InfoNCE loss, both directions. normalize->bf16; 128x128 CTA-tile HMMA GEMM
// (8 warps, 64x32 warp tiles, 3-stage cp.async pipeline, 2 CTAs/SM);
// fused exp + row/col sums; final log-reduce.
// ============================================================================
#define BATCH 16
#define NROWS 2048
#define DIMC  256
#define TOTAL_ROWS (BATCH * NROWS)            // 32768
#define TEMP_INV   10.0f

#define TILE_M 128
#define TILE_N 128
#define KC     64                              // K chunk
#define NSTEPS (DIMC / KC)                     // 4
#define STAGES 3

// warp grid: 2 (M) x 4 (N); warp tile 64x32
#define WM 64
#define WN 32

// Smem rows: KC bf16 + 8 pad = 144 B (conflict-free ldmatrix)
#define LDS_ROW_B 144
#define A_STAGE_BYTES (TILE_M * LDS_ROW_B)     // 18432
#define STAGE_BYTES   (2 * A_STAGE_BYTES)      // 36864 (A then B)
#define SMEM_TOTAL    (STAGES * STAGE_BYTES)   // 110592

// ============================================================================
// Device scratch
// ============================================================================
__device__ __align__(16) __nv_bfloat16 g_Abf[TOTAL_ROWS * DIMC];
__device__ __align__(16) __nv_bfloat16 g_Bbf[TOTAL_ROWS * DIMC];
__device__ float g_rowSum[TOTAL_ROWS];
__device__ float g_colSum[TOTAL_ROWS];
__device__ float g_diag[TOTAL_ROWS];

// ============================================================================
// Helpers
// ============================================================================
__device__ __forceinline__ uint32_t smem_u32(const void* p) {
    uint32_t a;
    asm("{ .reg .u64 t; cvta.to.shared.u64 t, %1; cvt.u32.u64 %0, t; }"
        : "=r"(a) : "l"(p));
    return a;
}

__device__ __forceinline__ uint32_t pack_bf16x2(float lo, float hi) {
    uint32_t r;
    asm("cvt.rn.bf16x2.f32 %0, %1, %2;" : "=r"(r) : "f"(hi), "f"(lo));
    return r;
}

#define CP_ASYNC16(dst, src) \
    asm volatile("cp.async.cg.shared.global [%0], [%1], 16;" :: "r"(dst), "l"(src))
#define CP_COMMIT() asm volatile("cp.async.commit_group;")
#define CP_WAIT(n)  asm volatile("cp.async.wait_group %0;" :: "n"(n) : "memory")

__device__ __forceinline__ void ldmatrix_x4(uint32_t& r0, uint32_t& r1,
                                            uint32_t& r2, uint32_t& r3,
                                            uint32_t addr) {
    asm volatile("ldmatrix.sync.aligned.m8n8.x4.shared.b16 {%0,%1,%2,%3}, [%4];"
                 : "=r"(r0), "=r"(r1), "=r"(r2), "=r"(r3) : "r"(addr));
}

__device__ __forceinline__ void mma_bf16(float* d, const uint32_t* a,
                                         const uint32_t* b, const float* c) {
    asm volatile(
        "mma.sync.aligned.m16n8k16.row.col.f32.bf16.bf16.f32 "
        "{%0,%1,%2,%3}, {%4,%5,%6,%7}, {%8,%9}, {%10,%11,%12,%13};"
        : "=f"(d[0]), "=f"(d[1]), "=f"(d[2]), "=f"(d[3])
        : "r"(a[0]), "r"(a[1]), "r"(a[2]), "r"(a[3]),
          "r"(b[0]), "r"(b[1]),
          "f"(c[0]), "f"(c[1]), "f"(c[2]), "f"(c[3]));
}

// ============================================================================
// Kernel 1: L2-normalize rows -> bf16; zero accumulators + out
// ============================================================================
__global__ void normalize_kernel(const float* __restrict__ A,
                                 const float* __restrict__ B,
                                 float* out) {
    int gwarp = (blockIdx.x * blockDim.x + threadIdx.x) >> 5;
    int lane = threadIdx.x & 31;
    if (gwarp >= 2 * TOTAL_ROWS) return;

    const float* src;
    __nv_bfloat16* dst;
    int row;
    if (gwarp < TOTAL_ROWS) {
        src = A; dst = g_Abf; row = gwarp;
        if (lane == 0) { g_rowSum[row] = 0.0f; g_colSum[row] = 0.0f; }
        if (gwarp == 0 && lane == 1) out[0] = 0.0f;
    } else {
        src = B; dst = g_Bbf; row = gwarp - TOTAL_ROWS;
    }

    const float4* p = reinterpret_cast<const float4*>(src + (size_t)row * DIMC);
    float4 v0 = p[lane * 2];
    float4 v1 = p[lane * 2 + 1];
    float ss = v0.x*v0.x + v0.y*v0.y + v0.z*v0.z + v0.w*v0.w
             + v1.x*v1.x + v1.y*v1.y + v1.z*v1.z + v1.w*v1.w;
    #pragma unroll
    for (int off = 16; off > 0; off >>= 1)
        ss += __shfl_xor_sync(0xFFFFFFFFu, ss, off);
    float rinv = rsqrtf(ss);

    uint32_t o0 = pack_bf16x2(v0.x * rinv, v0.y * rinv);
    uint32_t o1 = pack_bf16x2(v0.z * rinv, v0.w * rinv);
    uint32_t o2 = pack_bf16x2(v1.x * rinv, v1.y * rinv);
    uint32_t o3 = pack_bf16x2(v1.z * rinv, v1.w * rinv);
    reinterpret_cast<uint4*>(dst + (size_t)row * DIMC)[lane] =
        make_uint4(o0, o1, o2, o3);
}

// ============================================================================
// Kernel 2: 128x128 tile GEMM (HMMA bf16), 3-stage pipeline,
// fused exp + row/col reductions.  grid=(16,16,16) block=256, 2 CTA/SM
// ============================================================================
__device__ __forceinline__ void stage_issue(uint32_t sbase, int stage, int kc0,
                                            const __nv_bfloat16* gA,
                                            const __nv_bfloat16* gB, int tid) {
    uint32_t aDst = sbase + (uint32_t)stage * STAGE_BYTES;
    uint32_t bDst = aDst + A_STAGE_BYTES;
    // per operand: 128 rows x 8 chunks of 16B = 1024 chunks -> 4/thread
    #pragma unroll
    for (int t = 0; t < 4; t++) {
        int i = tid + t * 256;
        int row = i >> 3;
        int c16 = i & 7;
        uint32_t so = (uint32_t)row * LDS_ROW_B + c16 * 16;
        CP_ASYNC16(aDst + so, gA + (size_t)row * DIMC + kc0 + c16 * 8);
        CP_ASYNC16(bDst + so, gB + (size_t)row * DIMC + kc0 + c16 * 8);
    }
    CP_COMMIT();
}

__global__ void __launch_bounds__(256, 2)
gemm_nce_kernel() {
    extern __shared__ char smem[];
    uint32_t sbase = smem_u32(smem);
    int tid  = threadIdx.x;
    int wid  = tid >> 5;
    int lane = tid & 31;

    int b  = blockIdx.z;
    int m0 = blockIdx.y * TILE_M;
    int n0 = blockIdx.x * TILE_N;
    bool isDiag = (blockIdx.x == blockIdx.y);

    const __nv_bfloat16* gA = g_Abf + ((size_t)b * NROWS + m0) * DIMC;
    const __nv_bfloat16* gB = g_Bbf + ((size_t)b * NROWS + n0) * DIMC;

    int warp_m = wid & 1;               // 0..1 (64 rows)
    int warp_n = wid >> 1;              // 0..3 (32 cols)

    float acc[4][4][4];
    #pragma unroll
    for (int tm = 0; tm < 4; tm++)
        #pragma unroll
        for (int tn = 0; tn < 4; tn++)
            #pragma unroll
            for (int r = 0; r < 4; r++) acc[tm][tn][r] = 0.0f;

    int lm_row_a = lane & 15;
    int lm_koff_a = (lane >> 4) << 3;
    int lm_row_b = ((lane >> 4) << 3) + (lane & 7);
    int lm_koff_b = ((lane >> 3) & 1) << 3;

    // ---- Prologue: 2 stages in flight ----
    stage_issue(sbase, 0, 0,  gA, gB, tid);
    stage_issue(sbase, 1, KC, gA, gB, tid);

    #pragma unroll
    for (int s = 0; s < NSTEPS; s++) {
        // ensure stage s landed (allow up to 1 younger group pending)
        if (s + 1 < NSTEPS) { CP_WAIT(1); } else { CP_WAIT(0); }
        __syncthreads();
        // safe post-barrier: buffer (s+2)%3 == buffer of stage s-1, whose
        // readers all passed this barrier already
        if (s + 2 < NSTEPS)
            stage_issue(sbase, (s + 2) % STAGES, (s + 2) * KC, gA, gB, tid);

        uint32_t stg = (uint32_t)(s % STAGES) * STAGE_BYTES;
        uint32_t aBase = sbase + stg + (uint32_t)(warp_m * WM) * LDS_ROW_B;
        uint32_t bBase = sbase + stg + A_STAGE_BYTES
                       + (uint32_t)(warp_n * WN) * LDS_ROW_B;

        #pragma unroll
        for (int ks = 0; ks < KC / 16; ks++) {
            int k0 = ks * 16;
            uint32_t bf[4][2];
            #pragma unroll
            for (int half = 0; half < 2; half++) {
                uint32_t addr = bBase
                    + (uint32_t)(half * 16 + lm_row_b) * LDS_ROW_B
                    + (uint32_t)(k0 + lm_koff_b) * 2;
                ldmatrix_x4(bf[half*2][0], bf[half*2][1],
                            bf[half*2+1][0], bf[half*2+1][1], addr);
            }
            #pragma unroll
            for (int tm = 0; tm < 4; tm++) {
                uint32_t af[4];
                uint32_t addr = aBase
                    + (uint32_t)(tm * 16 + lm_row_a) * LDS_ROW_B
                    + (uint32_t)(k0 + lm_koff_a) * 2;
                ldmatrix_x4(af[0], af[1], af[2], af[3], addr);
                #pragma unroll
                for (int tn = 0; tn < 4; tn++)
                    mma_bf16(acc[tm][tn], af, bf[tn], acc[tm][tn]);
            }
        }
    }

    // ---- Epilogue: sim = 10*acc; exp; row/col sums; diag ----
    int rbase = warp_m * WM;
    int cbase = warp_n * WN;
    int rlane = lane >> 2;
    int clane = (lane & 3) * 2;

    float rowAcc[4][2];
    float colAcc[4][2];
    #pragma unroll
    for (int i = 0; i < 4; i++) { rowAcc[i][0]=rowAcc[i][1]=0.f; colAcc[i][0]=colAcc[i][1]=0.f; }

    #pragma unroll
    for (int tm = 0; tm < 4; tm++) {
        #pragma unroll
        for (int tn = 0; tn < 4; tn++) {
            #pragma unroll
            for (int r = 0; r < 4; r++) {
                int h = r >> 1, j = r & 1;
                float sim = TEMP_INV * acc[tm][tn][r];
                int lr = rbase + tm*16 + rlane + 8*h;
                int lc = cbase + tn*8 + clane + j;
                if (isDiag && lr == lc)
                    g_diag[(b << 11) + m0 + lr] = sim;
                float e = __expf(sim);
                rowAcc[tm][h] += e;
                colAcc[tn][j] += e;
            }
        }
    }

    // row sums: reduce over lane%4
    #pragma unroll
    for (int tm = 0; tm < 4; tm++)
        #pragma unroll
        for (int h = 0; h < 2; h++) {
            float v = rowAcc[tm][h];
            v += __shfl_xor_sync(0xFFFFFFFFu, v, 1);
            v += __shfl_xor_sync(0xFFFFFFFFu, v, 2);
            if ((lane & 3) == 0) {
                int lr = rbase + tm*16 + rlane + 8*h;
                atomicAdd(&g_rowSum[(b << 11) + m0 + lr], v);
            }
        }

    // col sums: reduce over lane/4
    #pragma unroll
    for (int tn = 0; tn < 4; tn++)
        #pragma unroll
        for (int j = 0; j < 2; j++) {
            float v = colAcc[tn][j];
            v += __shfl_xor_sync(0xFFFFFFFFu, v, 4);
            v += __shfl_xor_sync(0xFFFFFFFFu, v, 8);
            v += __shfl_xor_sync(0xFFFFFFFFu, v, 16);
            if (lane < 4) {
                int lc = cbase + tn*8 + clane + j;
                atomicAdd(&g_colSum[(b << 11) + n0 + lc], v);
            }
        }
}

// ============================================================================
// Kernel 3: final reduction  loss = mean(log rowSum + log colSum - 2*diag)
// ============================================================================
__global__ void reduce_kernel(float* out) {
    __shared__ float red[8];
    int i = blockIdx.x * blockDim.x + threadIdx.x;
    float v = 0.0f;
    if (i < TOTAL_ROWS)
        v = logf(g_rowSum[i]) + logf(g_colSum[i]) - 2.0f * g_diag[i];
    #pragma unroll
    for (int off = 16; off > 0; off >>= 1)
        v += __shfl_xor_sync(0xFFFFFFFFu, v, off);
    int lane = threadIdx.x & 31, wid = threadIdx.x >> 5;
    if (lane == 0) red[wid] = v;
    __syncthreads();
    if (wid == 0) {
        v = (lane < 8) ? red[lane] : 0.0f;
        #pragma unroll
        for (int off = 4; off > 0; off >>= 1)
            v += __shfl_xor_sync(0xFFFFFFFFu, v, off);
        if (lane == 0) atomicAdd(out, v * (1.0f / TOTAL_ROWS));
    }
}

// ============================================================================
// Launch
// ============================================================================
extern "C" void kernel_launch(void* const* d_in, const int* in_sizes, int n_in,
                              void* d_out, int out_size) {
    const float* A = (const float*)d_in[0];
    const float* B = (const float*)d_in[1];
    float* out = (float*)d_out;

    cudaFuncSetAttribute(gemm_nce_kernel,
                         cudaFuncAttributeMaxDynamicSharedMemorySize, SMEM_TOTAL);

    normalize_kernel<<<(2 * TOTAL_ROWS) / 8, 256>>>(A, B, out);

    dim3 grid(NROWS / TILE_N, NROWS / TILE_M, BATCH);   // (16, 16, 16)
    gemm_nce_kernel<<<grid, 256, SMEM_TOTAL>>>();

    reduce_kernel<<<(TOTAL_ROWS + 255) / 256, 256>>>(out);
}